// round 14
// baseline (speedup 1.0000x reference)
#include <cuda_runtime.h>
#include <cstdint>

#define BB 8192
#define LL 200
#define QQ 128
#define HH 128
#define GRID 148
#define NTHREADS 640
#define NWARPS 20

#define ROW_FLOATS (LL * HH)          // 25600
#define ROW_BYTES  (ROW_FLOATS * 4)   // 102400
#define W_BYTES    (QQ * HH * 4)      // 65536
#define SQ_PITCH   132                // padded query-row pitch (bank-conflict-free)

__device__ float g_qw[BB * HH];       // qw = query @ W (4 MB, L2-resident)

// ---------------------------------------------------------------------------
// PTX helpers
// ---------------------------------------------------------------------------
__device__ __forceinline__ uint32_t smem_u32(const void* p) {
    uint32_t a;
    asm("{ .reg .u64 t; cvta.to.shared.u64 t, %1; cvt.u32.u64 %0, t; }"
        : "=r"(a) : "l"(p));
    return a;
}
__device__ __forceinline__ void mbar_init(uint32_t mbar, uint32_t count) {
    asm volatile("mbarrier.init.shared.b64 [%0], %1;" :: "r"(mbar), "r"(count) : "memory");
}
__device__ __forceinline__ void mbar_expect_tx(uint32_t mbar, uint32_t bytes) {
    asm volatile("mbarrier.arrive.expect_tx.shared.b64 _, [%0], %1;"
                 :: "r"(mbar), "r"(bytes) : "memory");
}
__device__ __forceinline__ void bulk_g2s(uint32_t dst, const void* src,
                                         uint32_t bytes, uint32_t mbar) {
    asm volatile(
        "cp.async.bulk.shared::cta.global.mbarrier::complete_tx::bytes "
        "[%0], [%1], %2, [%3];"
        :: "r"(dst), "l"(src), "r"(bytes), "r"(mbar) : "memory");
}
__device__ __forceinline__ void mbar_wait(uint32_t mbar, uint32_t parity) {
    uint32_t done;
    asm volatile(
        "{\n .reg .pred p;\n"
        " mbarrier.try_wait.parity.acquire.cta.shared::cta.b64 p, [%1], %2, 0x989680;\n"
        " selp.b32 %0, 1, 0, p;\n}"
        : "=r"(done) : "r"(mbar), "r"(parity) : "memory");
    while (!done) {
        asm volatile(
            "{\n .reg .pred p;\n"
            " mbarrier.try_wait.parity.acquire.cta.shared::cta.b64 p, [%1], %2, 0x989680;\n"
            " selp.b32 %0, 1, 0, p;\n}"
            : "=r"(done) : "r"(mbar), "r"(parity) : "memory");
    }
}

// Packed f32x2 FMA (FFMA2) — only reachable via PTX; IEEE fp32 per half.
#define FMA_F32X2(d, a, b) \
    asm("fma.rn.f32x2 %0, %1, %2, %0;" : "+l"(d) : "l"(a), "l"(b))
#define PACK_SAME(d, fbits) \
    asm("mov.b64 %0, {%1, %1};" : "=l"(d) : "r"(fbits))
#define UNPACK2(lo, hi, p) \
    asm("mov.b64 {%0, %1}, %2;" : "=f"(lo), "=f"(hi) : "l"(p))

// ---------------------------------------------------------------------------
// Single persistent kernel. grid=148 (1 CTA/SM), 640 threads (20 warps).
//
// Prologue (~5us, overlapped with first row TMA):
//   - TMA row(bid) -> buf0 ; TMA W -> buf1[0:16384)
//   - LDG-stage this CTA's query rows -> buf1[16384:...) (pitch 132)
//   - warp-mapped 4-row f32x2 GEMM -> g_qw (own rows only)
// Main loop: IDENTICAL to the measured-138.6us R13 loop.
//
// SMEM (floats): buf0 [0,25600) | buf1 [25600,51200) | s_logits [51200,51456)
//   s_red [51456,51488) | s_flag @51488 | s_part [51492,54052) | mbar @54052
// ---------------------------------------------------------------------------
__global__ __launch_bounds__(NTHREADS, 1) void attn_fused_kernel(
    const float* __restrict__ query, const float* __restrict__ W,
    const float* __restrict__ hist,  const void* __restrict__ hlen,
    float* __restrict__ out)
{
    extern __shared__ float smem[];
    float*  bufs[2] = { smem, smem + ROW_FLOATS };
    float*  s_logits = smem + 2 * ROW_FLOATS;          // 51200 (e_l for l>=Lb)
    float*  s_red    = s_logits + 256;                 // 51456 (20 warp sums)
    int*    s_flag   = (int*)(s_red + 32);             // 51488
    float*  s_part   = s_red + 36;                     // 51492: [20][128]
    uint64_t* mbar   = (uint64_t*)(smem + 54052);      // byte 216208, 8B aligned

    const int tid  = threadIdx.x;
    const int warp = tid >> 5;
    const int lane = tid & 31;
    const int bid  = blockIdx.x;
    const int k    = lane & 7;      // column octet (0..7)  [main loop]
    const int r    = lane >> 3;     // row-in-group (0..3)

    // BB = 55*148 + 52: bid<52 -> 56 rows, else 55
    const int nrows = (bid < (BB - 148 * (BB / 148))) ? (BB / 148 + 1) : (BB / 148);

    const uint32_t m0 = smem_u32(&mbar[0]);
    const uint32_t m1 = smem_u32(&mbar[1]);
    const uint32_t mW = smem_u32(&mbar[2]);
    const uint32_t buf_a[2] = { smem_u32(bufs[0]), smem_u32(bufs[1]) };

    if (tid == 0) { mbar_init(m0, 1); mbar_init(m1, 1); mbar_init(mW, 1); }
    __syncthreads();

    // ---- prologue: kick off copies, stage query, GEMM -> g_qw ----
    if (tid == 0) {
        mbar_expect_tx(m0, ROW_BYTES);
        bulk_g2s(buf_a[0], hist + (size_t)bid * ROW_FLOATS, ROW_BYTES, m0);
        mbar_expect_tx(mW, W_BYTES);
        bulk_g2s(buf_a[1], W, W_BYTES, mW);            // sW = buf1[0:16384)
        // length dtype: int64 values in [0,200) -> all odd dwords zero
        const int* len32 = (const int*)hlen;
        int nz = 0;
#pragma unroll
        for (int i = 1; i < 256; i += 2) nz += (len32[i] != 0);
        *s_flag = (nz == 0) ? 1 : 0;
    }

    // stage this CTA's query rows (pitch 132 floats -> conflict-free GEMM reads)
    float* sQ = bufs[1] + QQ * HH;                      // 7392 floats used
    {
        const float4* Qg = (const float4*)query;
        for (int rr = warp; rr < nrows; rr += NWARPS) {
            const int b = bid + 148 * rr;
            *(float4*)&sQ[rr * SQ_PITCH + lane * 4] = Qg[(size_t)b * 32 + lane];
        }
    }
    mbar_wait(mW, 0);          // W resident in SMEM
    __syncthreads();           // sQ + s_flag visible

    // GEMM: warp g -> rows 4g..4g+3; lane (r, j4): row r, col-quad j4.
    // Per q, all 4 row-subsets broadcast the same 128B W chunk.
    if (warp < 14) {
        const int j4  = lane & 7;
        const int row = warp * 4 + r;
        const int rowc = (row < nrows) ? row : (nrows - 1);
        const float* sW  = bufs[1];
        const float* sQr = sQ + rowc * SQ_PITCH;
#pragma unroll
        for (int cb = 0; cb < 4; ++cb) {
            uint64_t a0 = 0ull, a1 = 0ull;
            const float* wbase = sW + cb * 32 + j4 * 4;
#pragma unroll 8
            for (int q = 0; q < QQ; ++q) {
                const uint64_t* wq = (const uint64_t*)(wbase + q * HH);
                uint64_t w0 = wq[0], w1 = wq[1];        // one LDS.128
                uint64_t qq; PACK_SAME(qq, __float_as_uint(sQr[q]));
                FMA_F32X2(a0, qq, w0);
                FMA_F32X2(a1, qq, w1);
            }
            if (row < nrows) {
                float o0, o1, o2, o3;
                UNPACK2(o0, o1, a0);
                UNPACK2(o2, o3, a1);
                float4 o = {o0, o1, o2, o3};
                const int b = bid + 148 * row;
                *(float4*)(g_qw + (size_t)b * HH + cb * 32 + j4 * 4) = o;
            }
        }
    }
    __syncthreads();           // buf1 free; g_qw (own rows) visible CTA-wide
    const int is64 = *s_flag;

    // ---- main loop (identical to R13's measured 138.6us loop) ----
    uint32_t ph0 = 0, ph1 = 0;
    int it = 0;
    for (int b = bid; b < BB; b += GRID, ++it) {
        const int cur = it & 1;

        // prefetch next row into the other buffer (consumed last iteration)
        const int bn = b + GRID;
        if (bn < BB && tid == 0) {
            const uint32_t mb = cur ? m0 : m1;
            mbar_expect_tx(mb, ROW_BYTES);
            bulk_g2s(buf_a[cur ^ 1], hist + (size_t)bn * ROW_FLOATS, ROW_BYTES, mb);
        }

        // prefetch qw fragment + length while the copy runs
        const float4* qw4 = (const float4*)(g_qw + (size_t)b * HH);
        float4 qv[4];
#pragma unroll
        for (int c = 0; c < 4; ++c) qv[c] = qw4[c * 8 + k];

        int Lb;
        if (is64) Lb = (int)((const long long*)hlen)[b];
        else      Lb = ((const int*)hlen)[b];
        const int g0 = Lb >> 2;      // first group with any unmasked row

        // wait current buffer
        if (cur == 0) { mbar_wait(m0, ph0); ph0 ^= 1; }
        else          { mbar_wait(m1, ph1); ph1 ^= 1; }

        const float4* s4 = (const float4*)bufs[cur];

        // ---- pass 1: e_l = exp(logit_l) for l >= Lb only; masked groups
        // skipped entirely, active groups rebalanced across warps.
        float wsum = 0.f;
        for (int g = g0 + warp; g < 50; g += NWARPS) {
            const int l = g * 4 + r;
            const float4* row4 = s4 + l * 32;
            float p = 0.f;
#pragma unroll
            for (int c = 0; c < 4; ++c) {
                float4 v = row4[c * 8 + k];
                p += v.x * qv[c].x + v.y * qv[c].y + v.z * qv[c].z + v.w * qv[c].w;
            }
            p += __shfl_xor_sync(0xffffffffu, p, 4);
            p += __shfl_xor_sync(0xffffffffu, p, 2);
            p += __shfl_xor_sync(0xffffffffu, p, 1);
            float e = 0.f;
            if (l >= Lb) e = __expf(p);        // boundary-group masked lanes: 0
            if (k == 0) { s_logits[l] = e; wsum += e; }
        }
        // combine k==0 lanes (0,8,16,24)
        wsum += __shfl_xor_sync(0xffffffffu, wsum, 16);
        wsum += __shfl_xor_sync(0xffffffffu, wsum, 8);
        if (lane == 0) s_red[warp] = wsum;
        __syncthreads();

        // private 1/tot: masked rows contribute exactly 1.0 each (exp(1e-9))
        float t0 = 0.f, t1 = 0.f, t2 = 0.f, t3 = 0.f;
#pragma unroll
        for (int w = 0; w < NWARPS; w += 4) {
            t0 += s_red[w]; t1 += s_red[w + 1]; t2 += s_red[w + 2]; t3 += s_red[w + 3];
        }
        const float inv = __frcp_rn((float)Lb + ((t0 + t1) + (t2 + t3)));

        // ---- pass 2: 10 iterations exactly (200/20); SMEM only ----
        float4 a4 = {0.f, 0.f, 0.f, 0.f};
#pragma unroll
        for (int i = 0; i < 10; ++i) {
            const int l = warp + i * NWARPS;
            const float sc = (l < Lb) ? 1.0f : s_logits[l];
            float4 v = s4[l * 32 + lane];
            a4.x = fmaf(sc, v.x, a4.x);
            a4.y = fmaf(sc, v.y, a4.y);
            a4.z = fmaf(sc, v.z, a4.z);
            a4.w = fmaf(sc, v.w, a4.w);
        }
        a4.x *= inv; a4.y *= inv; a4.z *= inv; a4.w *= inv;
        ((float4*)s_part)[warp * 32 + lane] = a4;
        __syncthreads();   // all buf[cur] reads done after this

        // ---- final reduce: 128 threads, conflict-free scalar columns ----
        if (tid < HH) {
            float vsum = 0.f;
#pragma unroll
            for (int g = 0; g < NWARPS; ++g) vsum += s_part[g * HH + tid];
            out[(size_t)b * HH + tid] = vsum;
        }
    }
}

// ---------------------------------------------------------------------------
extern "C" void kernel_launch(void* const* d_in, const int* in_sizes, int n_in,
                              void* d_out, int out_size) {
    // Bind inputs BY ELEMENT COUNT (all distinct) — immune to ordering.
    const float* query = nullptr;   // 1048576
    const float* hist  = nullptr;   // 209715200
    const void*  hlen  = nullptr;   // 8192
    const float* W     = nullptr;   // 16384
    for (int i = 0; i < n_in; ++i) {
        switch (in_sizes[i]) {
            case BB * QQ:      query = (const float*)d_in[i]; break;
            case BB * LL * HH: hist  = (const float*)d_in[i]; break;
            case BB:           hlen  = d_in[i];               break;
            case QQ * HH:      W     = (const float*)d_in[i]; break;
            default: break;
        }
    }
    float* out = (float*)d_out;

    const int smem = 54052 * 4 + 64;   // 216272 B

    cudaFuncSetAttribute(attn_fused_kernel,
                         cudaFuncAttributeMaxDynamicSharedMemorySize, smem);

    attn_fused_kernel<<<GRID, NTHREADS, smem>>>(query, W, hist, hlen, out);
}